// round 8
// baseline (speedup 1.0000x reference)
#include <cuda_runtime.h>
#include <cuda_bf16.h>
#include <cstdint>
#include <cstddef>

// ---------------- problem constants ----------------
#define BATCH   64
#define CIN     2048
#define LL      196
#define L1      197
#define HID     2048
#define OUTC    256
#define NHEADS  8
#define CKEYS   32
#define NN1     (BATCH * L1)    // 12608
#define NN2     (BATCH * CKEYS) // 2048
#define BN_EPS  1e-5f
#define NORM_EPS 1e-12f

// output layout: z_g | obj_val | obj_attn | obj_attn_raw
#define OFF_ZG      0
#define OFF_OBJVAL  (BATCH * OUTC)
#define OFF_ATTN    (OFF_OBJVAL + BATCH * OUTC * CKEYS)
#define OFF_ATTN2   (OFF_ATTN + BATCH * NHEADS * CKEYS * LL)

// ---------------- scratch (static; no allocs) ----------------
// bf16 hi/lo plane pairs (lo plane at +plane_size)
__device__ __align__(16) __nv_bfloat16 g_w1pT[2 * (size_t)HID * CIN];
__device__ __align__(16) __nv_bfloat16 g_w2pT[2 * (size_t)OUTC * HID];
__device__ __align__(16) __nv_bfloat16 g_w1oT[2 * (size_t)HID * CIN];
__device__ __align__(16) __nv_bfloat16 g_w2oT[2 * (size_t)OUTC * HID];
__device__ __align__(16) __nv_bfloat16 g_xcatT[2 * (size_t)NN1 * CIN];
__device__ __align__(16) __nv_bfloat16 g_h1T[2 * (size_t)NN1 * HID];
__device__ __align__(16) __nv_bfloat16 g_objT[2 * (size_t)NN2 * CIN];
__device__ __align__(16) __nv_bfloat16 g_h2T[2 * (size_t)NN2 * HID];
// fp32
__device__ __align__(16) float g_h1[(size_t)HID * NN1];
__device__ __align__(16) float g_z[(size_t)OUTC * NN1];
__device__ __align__(16) float g_rnrm[BATCH * LL];
__device__ __align__(16) float g_attn[(size_t)BATCH * OUTC * LL];
__device__ __align__(16) float g_h2[(size_t)HID * NN2];
__device__ __align__(16) float g_ov[(size_t)OUTC * NN2];
__device__ __align__(16) float g_scale[HID];
__device__ __align__(16) float g_shift[HID];

// ---------------- helpers ----------------
__device__ __forceinline__ void split2(float v, __nv_bfloat16& h, __nv_bfloat16& l) {
    h = __float2bfloat16(v);
    l = __float2bfloat16(v - __bfloat162float(h));
}

// ---------------- weight split (fp32 [M][K] -> bf16 hi/lo planes) ----------------
__global__ void split_kernel(const float* __restrict__ in, __nv_bfloat16* __restrict__ out, int n)
{
    int i = (blockIdx.x * blockDim.x + threadIdx.x) * 4;
    if (i >= n) return;
    float4 v = *(const float4*)(in + i);
    __nv_bfloat16 h0, l0, h1, l1, h2, l2, h3, l3;
    split2(v.x, h0, l0); split2(v.y, h1, l1);
    split2(v.z, h2, l2); split2(v.w, h3, l3);
    __nv_bfloat162* ph = (__nv_bfloat162*)(out + i);
    ph[0] = __nv_bfloat162(h0, h1); ph[1] = __nv_bfloat162(h2, h3);
    __nv_bfloat162* pl = (__nv_bfloat162*)(out + n + i);
    pl[0] = __nv_bfloat162(l0, l1); pl[1] = __nv_bfloat162(l2, l3);
}

// ---------------- xcat prep: x(b,c,l) -> xcatT[n=b*197+{0|1+l}][c] hi/lo ----------------
__global__ __launch_bounds__(256)
void xcat_prep_kernel(const float* __restrict__ x, __nv_bfloat16* __restrict__ xT)
{
    __shared__ float xs[32][197];
    int b = blockIdx.y, c0 = blockIdx.x * 32;
    const float* xp = x + ((size_t)b * CIN + c0) * LL;
    for (int i = threadIdx.x; i < 32 * LL; i += 256) {
        int ci = i / LL, l = i % LL;
        xs[ci][1 + l] = xp[(size_t)ci * LL + l];
    }
    __syncthreads();
    if (threadIdx.x < 32) {
        float s = 0.f;
        for (int l = 1; l <= LL; l++) s += xs[threadIdx.x][l];
        xs[threadIdx.x][0] = s * (1.0f / (float)LL);
    }
    __syncthreads();
    const size_t plane = (size_t)NN1 * CIN;
    for (int i = threadIdx.x; i < L1 * 32; i += 256) {
        int li = i >> 5, ci = i & 31;
        __nv_bfloat16 h, l;
        split2(xs[ci][li], h, l);
        size_t o = (size_t)(b * L1 + li) * CIN + c0 + ci;
        xT[o] = h; xT[plane + o] = l;
    }
}

// ---------------- transpose + BN + relu + split: H[o][n] -> Ht[n][o] hi/lo ----------------
__global__ __launch_bounds__(256)
void tbs_kernel(const float* __restrict__ H, int Mrows, int Ncols,
                const float* __restrict__ scale, const float* __restrict__ shift,
                __nv_bfloat16* __restrict__ Ht)
{
    __shared__ float t[32][33];
    int n0 = blockIdx.x * 32, o0 = blockIdx.y * 32;
    int tx = threadIdx.x & 31, ty = threadIdx.x >> 5;
    #pragma unroll
    for (int j = 0; j < 4; j++) {
        int o = o0 + ty + j * 8;
        float v = H[(size_t)o * Ncols + n0 + tx];
        t[ty + j * 8][tx] = fmaxf(fmaf(v, scale[o], shift[o]), 0.f);
    }
    __syncthreads();
    const size_t plane = (size_t)Ncols * Mrows;
    #pragma unroll
    for (int j = 0; j < 4; j++) {
        int n = n0 + ty + j * 8;
        __nv_bfloat16 h, l;
        split2(t[tx][ty + j * 8], h, l);
        size_t o = (size_t)n * Mrows + o0 + tx;
        Ht[o] = h; Ht[plane + o] = l;
    }
}

// ---------------- bf16-split tensor-core GEMM (cp.async, pass-major MMA) ----------------
// C(MxN) fp32 = A(MxK) * B(NxK)^T via hi/lo planes.
#define BMg 128
#define BNg 64
#define BKg 32
#define PITg 40
#define A_OFF_L 5120
#define B_OFF_H 10240
#define B_OFF_L 12800
#define STAGE_E 15360
#define SMEM_BYTES (2 * STAGE_E * 2)   // 61440

#define LDSM_X4(r0, r1, r2, r3, addr) \
    asm volatile("ldmatrix.sync.aligned.m8n8.x4.shared.b16 {%0,%1,%2,%3}, [%4];" \
        : "=r"(r0), "=r"(r1), "=r"(r2), "=r"(r3) : "r"(addr))

#define MMA16816(d, a, b0, b1) \
    asm volatile("mma.sync.aligned.m16n8k16.row.col.f32.bf16.bf16.f32 " \
        "{%0,%1,%2,%3},{%4,%5,%6,%7},{%8,%9},{%0,%1,%2,%3};" \
        : "+f"(d[0]), "+f"(d[1]), "+f"(d[2]), "+f"(d[3]) \
        : "r"(a[0]), "r"(a[1]), "r"(a[2]), "r"(a[3]), "r"(b0), "r"(b1))

#define CP16(dst, src) \
    asm volatile("cp.async.cg.shared.global [%0], [%1], 16;" :: "r"(dst), "l"(src))
#define CPCOMMIT() asm volatile("cp.async.commit_group;")
#define CPWAIT1()  asm volatile("cp.async.wait_group 1;")
#define CPWAIT0()  asm volatile("cp.async.wait_group 0;")

__global__ __launch_bounds__(256)
void gemm_ts_kernel(const __nv_bfloat16* __restrict__ Ahl,
                    const __nv_bfloat16* __restrict__ Bhl,
                    float* __restrict__ Cm, int M, int N, int K)
{
    extern __shared__ __align__(16) __nv_bfloat16 sm[];
    const int tid  = threadIdx.x;
    const int lane = tid & 31, wid = tid >> 5;
    const int warp_m = (wid & 3) * 32, warp_n = (wid >> 2) * 32;
    const int bm = blockIdx.y * BMg, bn = blockIdx.x * BNg;
    const size_t Apl = (size_t)M * K;
    const size_t Bpl = (size_t)N * K;

    // loader decomposition: chunk row = tid>>2, k offset = (tid&3)*8 (16B chunk)
    const int lr = tid >> 2, lk = (tid & 3) << 3;
    const __nv_bfloat16* Ag = Ahl + (size_t)(bm + lr) * K + lk;
    const __nv_bfloat16* Bg = Bhl + (size_t)(bn + lr) * K + lk;

    const uint32_t smbase = (uint32_t)__cvta_generic_to_shared(sm);

    // ldmatrix lane decomposition
    const int q = lane & 7, tt = lane >> 3;
    const int a_row = warp_m + (tt & 1) * 8 + q;
    const int a_col = (tt >> 1) * 8;
    const int b_row = warp_n + (tt >> 1) * 8 + q;
    const int b_col = (tt & 1) * 8;

    float acc[2][4][4];
    #pragma unroll
    for (int i = 0; i < 2; i++)
        #pragma unroll
        for (int j = 0; j < 4; j++)
            #pragma unroll
            for (int r = 0; r < 4; r++) acc[i][j][r] = 0.f;

    auto issue = [&](int k0, int s) {
        uint32_t so = smbase + (uint32_t)s * (STAGE_E * 2);
        CP16(so + (lr * PITg + lk) * 2,                     Ag + k0);
        CP16(so + ((lr + 64) * PITg + lk) * 2,              Ag + (size_t)64 * K + k0);
        CP16(so + (A_OFF_L + lr * PITg + lk) * 2,           Ag + Apl + k0);
        CP16(so + (A_OFF_L + (lr + 64) * PITg + lk) * 2,    Ag + Apl + (size_t)64 * K + k0);
        CP16(so + (B_OFF_H + lr * PITg + lk) * 2,           Bg + k0);
        CP16(so + (B_OFF_L + lr * PITg + lk) * 2,           Bg + Bpl + k0);
    };

    auto compute = [&](int s) {
        const uint32_t off = (uint32_t)s * STAGE_E;
        #pragma unroll
        for (int kk = 0; kk < BKg; kk += 16) {
            uint32_t ah[2][4], al[2][4], bh[2][4], bl[2][4];
            #pragma unroll
            for (int mf = 0; mf < 2; mf++) {
                uint32_t ad = smbase + (off + (a_row + mf * 16) * PITg + kk + a_col) * 2;
                LDSM_X4(ah[mf][0], ah[mf][1], ah[mf][2], ah[mf][3], ad);
                LDSM_X4(al[mf][0], al[mf][1], al[mf][2], al[mf][3], ad + A_OFF_L * 2);
            }
            #pragma unroll
            for (int pf = 0; pf < 2; pf++) {
                uint32_t bd = smbase + (off + B_OFF_H + (b_row + pf * 16) * PITg + kk + b_col) * 2;
                LDSM_X4(bh[pf][0], bh[pf][1], bh[pf][2], bh[pf][3], bd);
                LDSM_X4(bl[pf][0], bl[pf][1], bl[pf][2], bl[pf][3], bd + (B_OFF_L - B_OFF_H) * 2);
            }
            // pass-major: 8 independent MMAs between accumulator reuses
            #pragma unroll
            for (int mf = 0; mf < 2; mf++)
                #pragma unroll
                for (int nf = 0; nf < 4; nf++)
                    MMA16816(acc[mf][nf], ah[mf], bh[nf >> 1][2 * (nf & 1)], bh[nf >> 1][2 * (nf & 1) + 1]);
            #pragma unroll
            for (int mf = 0; mf < 2; mf++)
                #pragma unroll
                for (int nf = 0; nf < 4; nf++)
                    MMA16816(acc[mf][nf], al[mf], bh[nf >> 1][2 * (nf & 1)], bh[nf >> 1][2 * (nf & 1) + 1]);
            #pragma unroll
            for (int mf = 0; mf < 2; mf++)
                #pragma unroll
                for (int nf = 0; nf < 4; nf++)
                    MMA16816(acc[mf][nf], ah[mf], bl[nf >> 1][2 * (nf & 1)], bl[nf >> 1][2 * (nf & 1) + 1]);
        }
    };

    const int nst = K / BKg;
    issue(0, 0); CPCOMMIT();
    issue(BKg, 1); CPCOMMIT();

    for (int s = 0; s < nst; s++) {
        if (s + 1 < nst) { CPWAIT1(); } else { CPWAIT0(); }
        __syncthreads();
        compute(s & 1);
        __syncthreads();
        if (s + 2 < nst) { issue((s + 2) * BKg, s & 1); CPCOMMIT(); }
    }

    const int g = lane >> 2, t2 = (lane & 3) * 2;
    #pragma unroll
    for (int mf = 0; mf < 2; mf++) {
        #pragma unroll
        for (int nf = 0; nf < 4; nf++) {
            int row = bm + warp_m + mf * 16 + g;
            int col = bn + warp_n + nf * 8 + t2;
            *(float2*)(Cm + (size_t)row * N + col)       = make_float2(acc[mf][nf][0], acc[mf][nf][1]);
            *(float2*)(Cm + (size_t)(row + 8) * N + col) = make_float2(acc[mf][nf][2], acc[mf][nf][3]);
        }
    }
}

// ---------------- per-channel BN stats ----------------
__global__ void bn_stats_kernel(const float* __restrict__ Hm, int N,
                                const float* __restrict__ gamma, const float* __restrict__ beta,
                                float* __restrict__ scale, float* __restrict__ shift)
{
    int o = blockIdx.x;
    const float* row = Hm + (size_t)o * N;
    float s = 0.f, sq = 0.f;
    for (int i = threadIdx.x; i < N; i += blockDim.x) {
        float v = row[i];
        s += v; sq = fmaf(v, v, sq);
    }
    __shared__ float sh1[256], sh2[256];
    sh1[threadIdx.x] = s; sh2[threadIdx.x] = sq;
    __syncthreads();
    for (int off = 128; off > 0; off >>= 1) {
        if (threadIdx.x < off) {
            sh1[threadIdx.x] += sh1[threadIdx.x + off];
            sh2[threadIdx.x] += sh2[threadIdx.x + off];
        }
        __syncthreads();
    }
    if (threadIdx.x == 0) {
        float invN = 1.0f / (float)N;
        float mu  = sh1[0] * invN;
        float var = sh2[0] * invN - mu * mu;
        float sc  = gamma[o] * rsqrtf(var + BN_EPS);
        scale[o] = sc;
        shift[o] = beta[o] - mu * sc;
    }
}

// ---------------- z_g extraction ----------------
__global__ void zg_kernel(const float* __restrict__ z, float* __restrict__ out)
{
    int i = blockIdx.x * blockDim.x + threadIdx.x;
    if (i >= BATCH * OUTC) return;
    int b = i / OUTC, ch = i % OUTC;
    out[OFF_ZG + i] = z[(size_t)ch * NN1 + b * L1];
}

// ---------------- 1/max(||z_feat||,eps) per (b,l) ----------------
__global__ void rnrm_kernel(const float* __restrict__ z, float* __restrict__ rnrm)
{
    int idx = blockIdx.x * blockDim.x + threadIdx.x;
    if (idx >= BATCH * LL) return;
    int b = idx / LL, l = idx % LL;
    const float* zp = z + (size_t)b * L1 + 1 + l;
    float s = 0.f;
    #pragma unroll 8
    for (int ch = 0; ch < OUTC; ch++) {
        float v = zp[(size_t)ch * NN1];
        s = fmaf(v, v, s);
    }
    rnrm[idx] = 1.0f / fmaxf(sqrtf(s), NORM_EPS);
}

// ---------------- softmax ----------------
__global__ void softmax_kernel(const float* __restrict__ z, const float* __restrict__ rnrm,
                               float* __restrict__ attn_s, float* __restrict__ out)
{
    int row = blockIdx.x;
    int b = row >> 8, ch = row & 255;
    int tid = threadIdx.x;
    const float* zp = z + (size_t)ch * NN1 + b * L1 + 1;
    const float* rp = rnrm + b * LL;

    float v0 = -1e30f, v1 = -1e30f;
    if (tid < LL)       v0 = zp[tid]       * rp[tid];
    if (tid + 128 < LL) v1 = zp[tid + 128] * rp[tid + 128];

    __shared__ float red[128];
    red[tid] = fmaxf(v0, v1);
    __syncthreads();
    for (int off = 64; off > 0; off >>= 1) {
        if (tid < off) red[tid] = fmaxf(red[tid], red[tid + off]);
        __syncthreads();
    }
    float m = red[0];
    __syncthreads();

    float e0 = (tid < LL)       ? expf(v0 - m) : 0.f;
    float e1 = (tid + 128 < LL) ? expf(v1 - m) : 0.f;
    red[tid] = e0 + e1;
    __syncthreads();
    for (int off = 64; off > 0; off >>= 1) {
        if (tid < off) red[tid] += red[tid + off];
        __syncthreads();
    }
    float inv = 1.0f / red[0];

    size_t base = (size_t)row * LL;
    if (tid < LL) {
        float a = e0 * inv;
        attn_s[base + tid] = a;
        out[OFF_ATTN  + base + tid] = a;
        out[OFF_ATTN2 + base + tid] = a;
    }
    if (tid + 128 < LL) {
        float a = e1 * inv;
        attn_s[base + tid + 128] = a;
        out[OFF_ATTN  + base + tid + 128] = a;
        out[OFF_ATTN2 + base + tid + 128] = a;
    }
}

// ---------------- obj_val einsum -> objT[n2][c] hi/lo (split + transposed) ----------------
__global__ __launch_bounds__(512)
void objval_kernel(const float* __restrict__ x, const float* __restrict__ attn,
                   __nv_bfloat16* __restrict__ objT)
{
    __shared__ float xs[16][LL];
    __shared__ float as[32][LL];
    int b  = blockIdx.z;
    int h  = blockIdx.y;
    int cg = blockIdx.x;
    int tid = threadIdx.x;

    const float* ap = attn + ((size_t)b * OUTC + h * CKEYS) * LL;
    for (int i = tid; i < 32 * LL; i += 512) as[i / LL][i % LL] = ap[i];
    const float* xp = x + ((size_t)b * CIN + h * 256 + cg * 16) * LL;
    for (int i = tid; i < 16 * LL; i += 512) xs[i / LL][i % LL] = xp[i];
    __syncthreads();

    int ci = tid & 15, k = tid >> 4;
    float acc = 0.f;
    #pragma unroll 4
    for (int l = 0; l < LL; l++) acc = fmaf(xs[ci][l], as[k][l], acc);

    int c = h * 256 + cg * 16 + ci;
    const size_t plane = (size_t)NN2 * CIN;
    size_t o = (size_t)(b * CKEYS + k) * CIN + c;
    __nv_bfloat16 hh, ll;
    split2(acc, hh, ll);
    objT[o] = hh; objT[plane + o] = ll;
}

// ---------------- final scatter of obj_val ----------------
__global__ void scatter_out_kernel(const float* __restrict__ ov, float* __restrict__ out)
{
    int i = blockIdx.x * blockDim.x + threadIdx.x;
    if (i >= BATCH * OUTC * CKEYS) return;
    int b = i / (OUTC * CKEYS);
    int r = i % (OUTC * CKEYS);
    int o2 = r / CKEYS, k = r % CKEYS;
    out[OFF_OBJVAL + i] = ov[(size_t)o2 * NN2 + b * CKEYS + k];
}

// ---------------- launch ----------------
extern "C" void kernel_launch(void* const* d_in, const int* in_sizes, int n_in,
                              void* d_out, int out_size)
{
    const float* x    = (const float*)d_in[0];
    const float* w1_p = (const float*)d_in[1];
    const float* g_p  = (const float*)d_in[2];
    const float* b_p  = (const float*)d_in[3];
    const float* w2_p = (const float*)d_in[4];
    const float* w1_o = (const float*)d_in[5];
    const float* g_o  = (const float*)d_in[6];
    const float* b_o  = (const float*)d_in[7];
    const float* w2_o = (const float*)d_in[8];
    float* out = (float*)d_out;

    __nv_bfloat16 *w1pT, *w2pT, *w1oT, *w2oT, *xcatT, *h1T, *objT, *h2T;
    float *h1, *z, *rn, *attn, *h2, *ov, *scale, *shift;
    cudaGetSymbolAddress((void**)&w1pT,  g_w1pT);
    cudaGetSymbolAddress((void**)&w2pT,  g_w2pT);
    cudaGetSymbolAddress((void**)&w1oT,  g_w1oT);
    cudaGetSymbolAddress((void**)&w2oT,  g_w2oT);
    cudaGetSymbolAddress((void**)&xcatT, g_xcatT);
    cudaGetSymbolAddress((void**)&h1T,   g_h1T);
    cudaGetSymbolAddress((void**)&objT,  g_objT);
    cudaGetSymbolAddress((void**)&h2T,   g_h2T);
    cudaGetSymbolAddress((void**)&h1,    g_h1);
    cudaGetSymbolAddress((void**)&z,     g_z);
    cudaGetSymbolAddress((void**)&rn,    g_rnrm);
    cudaGetSymbolAddress((void**)&attn,  g_attn);
    cudaGetSymbolAddress((void**)&h2,    g_h2);
    cudaGetSymbolAddress((void**)&ov,    g_ov);
    cudaGetSymbolAddress((void**)&scale, g_scale);
    cudaGetSymbolAddress((void**)&shift, g_shift);

    cudaFuncSetAttribute(gemm_ts_kernel,
                         cudaFuncAttributeMaxDynamicSharedMemorySize, SMEM_BYTES);

    // 0) weight splits
    split_kernel<<<(HID * CIN / 4 + 255) / 256, 256>>>(w1_p, w1pT, HID * CIN);
    split_kernel<<<(OUTC * HID / 4 + 255) / 256, 256>>>(w2_p, w2pT, OUTC * HID);
    split_kernel<<<(HID * CIN / 4 + 255) / 256, 256>>>(w1_o, w1oT, HID * CIN);
    split_kernel<<<(OUTC * HID / 4 + 255) / 256, 256>>>(w2_o, w2oT, OUTC * HID);

    // 1) xcatT = [mean | x] transposed + split
    xcat_prep_kernel<<<dim3(CIN / 32, BATCH), 256>>>(x, xcatT);

    // 2) h1 = w1_p @ xcat
    gemm_ts_kernel<<<dim3(NN1 / BNg, HID / BMg), 256, SMEM_BYTES>>>(
        w1pT, xcatT, h1, HID, NN1, CIN);

    // 3) BN stats
    bn_stats_kernel<<<HID, 256>>>(h1, NN1, g_p, b_p, scale, shift);

    // 3b) h1T = split(relu(bn(h1)))^T
    tbs_kernel<<<dim3(NN1 / 32, HID / 32), 256>>>(h1, HID, NN1, scale, shift, h1T);

    // 4) z = w2_p @ relu(bn(h1))
    gemm_ts_kernel<<<dim3(NN1 / BNg, OUTC / BMg), 256, SMEM_BYTES>>>(
        w2pT, h1T, z, OUTC, NN1, HID);

    // 5) z_g
    zg_kernel<<<(BATCH * OUTC + 255) / 256, 256>>>(z, out);

    // 6) 1/||z_feat||
    rnrm_kernel<<<(BATCH * LL + 255) / 256, 256>>>(z, rn);

    // 7) softmax
    softmax_kernel<<<BATCH * OUTC, 128>>>(z, rn, attn, out);

    // 8) obj_val einsum -> objT (split + transposed)
    objval_kernel<<<dim3(16, NHEADS, BATCH), 512>>>(x, attn, objT);

    // 9) h2 = w1_o @ objval
    gemm_ts_kernel<<<dim3(NN2 / BNg, HID / BMg), 256, SMEM_BYTES>>>(
        w1oT, objT, h2, HID, NN2, CIN);

    // 10) BN stats
    bn_stats_kernel<<<HID, 256>>>(h2, NN2, g_o, b_o, scale, shift);

    // 10b) h2T
    tbs_kernel<<<dim3(NN2 / 32, HID / 32), 256>>>(h2, HID, NN2, scale, shift, h2T);

    // 11) ov = w2_o @ relu(bn(h2))
    gemm_ts_kernel<<<dim3(NN2 / BNg, OUTC / BMg), 256, SMEM_BYTES>>>(
        w2oT, h2T, ov, OUTC, NN2, HID);

    // 12) scatter obj_val
    scatter_out_kernel<<<(BATCH * OUTC * CKEYS + 255) / 256, 256>>>(ov, out);
}

// round 10
// speedup vs baseline: 1.0022x; 1.0022x over previous
#include <cuda_runtime.h>
#include <cuda_bf16.h>
#include <cstdint>
#include <cstddef>

// ---------------- problem constants ----------------
#define BATCH   64
#define CIN     2048
#define LL      196
#define L1      197
#define HID     2048
#define OUTC    256
#define NHEADS  8
#define CKEYS   32
#define NN1     (BATCH * L1)    // 12608
#define NN2     (BATCH * CKEYS) // 2048
#define BN_EPS  1e-5f
#define NORM_EPS 1e-12f

// output layout: z_g | obj_val | obj_attn | obj_attn_raw
#define OFF_ZG      0
#define OFF_OBJVAL  (BATCH * OUTC)
#define OFF_ATTN    (OFF_OBJVAL + BATCH * OUTC * CKEYS)
#define OFF_ATTN2   (OFF_ATTN + BATCH * NHEADS * CKEYS * LL)

// ---------------- scratch (static; no allocs) ----------------
// bf16 hi/lo plane pairs (lo plane at +plane_size)
__device__ __align__(16) __nv_bfloat16 g_w1pT[2 * (size_t)HID * CIN];
__device__ __align__(16) __nv_bfloat16 g_w2pT[2 * (size_t)OUTC * HID];
__device__ __align__(16) __nv_bfloat16 g_w1oT[2 * (size_t)HID * CIN];
__device__ __align__(16) __nv_bfloat16 g_w2oT[2 * (size_t)OUTC * HID];
__device__ __align__(16) __nv_bfloat16 g_xcatT[2 * (size_t)NN1 * CIN];
__device__ __align__(16) __nv_bfloat16 g_h1T[2 * (size_t)NN1 * HID];
__device__ __align__(16) __nv_bfloat16 g_objT[2 * (size_t)NN2 * CIN];
__device__ __align__(16) __nv_bfloat16 g_h2T[2 * (size_t)NN2 * HID];
// fp32
__device__ __align__(16) float g_h1[(size_t)HID * NN1];
__device__ __align__(16) float g_z[(size_t)OUTC * NN1];
__device__ __align__(16) float g_rnrm[BATCH * LL];
__device__ __align__(16) float g_attn[(size_t)BATCH * OUTC * LL];
__device__ __align__(16) float g_h2[(size_t)HID * NN2];
__device__ __align__(16) float g_ov[(size_t)OUTC * NN2];
__device__ __align__(16) float g_scale[HID];
__device__ __align__(16) float g_shift[HID];

// ---------------- helpers ----------------
__device__ __forceinline__ void split2(float v, __nv_bfloat16& h, __nv_bfloat16& l) {
    h = __float2bfloat16(v);
    l = __float2bfloat16(v - __bfloat162float(h));
}

// ---------------- weight split (fp32 [M][K] -> bf16 hi/lo planes) ----------------
__global__ void split_kernel(const float* __restrict__ in, __nv_bfloat16* __restrict__ out, int n)
{
    int i = (blockIdx.x * blockDim.x + threadIdx.x) * 4;
    if (i >= n) return;
    float4 v = *(const float4*)(in + i);
    __nv_bfloat16 h0, l0, h1, l1, h2, l2, h3, l3;
    split2(v.x, h0, l0); split2(v.y, h1, l1);
    split2(v.z, h2, l2); split2(v.w, h3, l3);
    __nv_bfloat162* ph = (__nv_bfloat162*)(out + i);
    ph[0] = __nv_bfloat162(h0, h1); ph[1] = __nv_bfloat162(h2, h3);
    __nv_bfloat162* pl = (__nv_bfloat162*)(out + n + i);
    pl[0] = __nv_bfloat162(l0, l1); pl[1] = __nv_bfloat162(l2, l3);
}

// ---------------- xcat prep: x(b,c,l) -> xcatT[n=b*197+{0|1+l}][c] hi/lo ----------------
__global__ __launch_bounds__(256)
void xcat_prep_kernel(const float* __restrict__ x, __nv_bfloat16* __restrict__ xT)
{
    __shared__ float xs[32][197];
    int b = blockIdx.y, c0 = blockIdx.x * 32;
    const float* xp = x + ((size_t)b * CIN + c0) * LL;
    for (int i = threadIdx.x; i < 32 * LL; i += 256) {
        int ci = i / LL, l = i % LL;
        xs[ci][1 + l] = xp[(size_t)ci * LL + l];
    }
    __syncthreads();
    if (threadIdx.x < 32) {
        float s = 0.f;
        for (int l = 1; l <= LL; l++) s += xs[threadIdx.x][l];
        xs[threadIdx.x][0] = s * (1.0f / (float)LL);
    }
    __syncthreads();
    const size_t plane = (size_t)NN1 * CIN;
    for (int i = threadIdx.x; i < L1 * 32; i += 256) {
        int li = i >> 5, ci = i & 31;
        __nv_bfloat16 h, l;
        split2(xs[ci][li], h, l);
        size_t o = (size_t)(b * L1 + li) * CIN + c0 + ci;
        xT[o] = h; xT[plane + o] = l;
    }
}

// ---------------- transpose + BN + relu + split: H[o][n] -> Ht[n][o] hi/lo ----------------
__global__ __launch_bounds__(256)
void tbs_kernel(const float* __restrict__ H, int Mrows, int Ncols,
                const float* __restrict__ scale, const float* __restrict__ shift,
                __nv_bfloat16* __restrict__ Ht)
{
    __shared__ float t[32][33];
    int n0 = blockIdx.x * 32, o0 = blockIdx.y * 32;
    int tx = threadIdx.x & 31, ty = threadIdx.x >> 5;
    #pragma unroll
    for (int j = 0; j < 4; j++) {
        int o = o0 + ty + j * 8;
        float v = H[(size_t)o * Ncols + n0 + tx];
        t[ty + j * 8][tx] = fmaxf(fmaf(v, scale[o], shift[o]), 0.f);
    }
    __syncthreads();
    const size_t plane = (size_t)Ncols * Mrows;
    #pragma unroll
    for (int j = 0; j < 4; j++) {
        int n = n0 + ty + j * 8;
        __nv_bfloat16 h, l;
        split2(t[tx][ty + j * 8], h, l);
        size_t o = (size_t)n * Mrows + o0 + tx;
        Ht[o] = h; Ht[plane + o] = l;
    }
}

// ---------------- bf16-split tensor-core GEMM (cp.async, pass-major MMA) ----------------
// C(MxN) fp32 = A(MxK) * B(NxK)^T via hi/lo planes.
#define BMg 128
#define BNg 64
#define BKg 32
#define PITg 40
#define A_OFF_L 5120
#define B_OFF_H 10240
#define B_OFF_L 12800
#define STAGE_E 15360
#define SMEM_BYTES (2 * STAGE_E * 2)   // 61440

#define LDSM_X4(r0, r1, r2, r3, addr) \
    asm volatile("ldmatrix.sync.aligned.m8n8.x4.shared.b16 {%0,%1,%2,%3}, [%4];" \
        : "=r"(r0), "=r"(r1), "=r"(r2), "=r"(r3) : "r"(addr))

#define MMA16816(d, a, b0, b1) \
    asm volatile("mma.sync.aligned.m16n8k16.row.col.f32.bf16.bf16.f32 " \
        "{%0,%1,%2,%3},{%4,%5,%6,%7},{%8,%9},{%0,%1,%2,%3};" \
        : "+f"(d[0]), "+f"(d[1]), "+f"(d[2]), "+f"(d[3]) \
        : "r"(a[0]), "r"(a[1]), "r"(a[2]), "r"(a[3]), "r"(b0), "r"(b1))

#define CP16(dst, src) \
    asm volatile("cp.async.cg.shared.global [%0], [%1], 16;" :: "r"(dst), "l"(src))
#define CPCOMMIT() asm volatile("cp.async.commit_group;")
#define CPWAIT1()  asm volatile("cp.async.wait_group 1;")
#define CPWAIT0()  asm volatile("cp.async.wait_group 0;")

__global__ __launch_bounds__(256)
void gemm_ts_kernel(const __nv_bfloat16* __restrict__ Ahl,
                    const __nv_bfloat16* __restrict__ Bhl,
                    float* __restrict__ Cm, int M, int N, int K)
{
    extern __shared__ __align__(16) __nv_bfloat16 sm[];
    const int tid  = threadIdx.x;
    const int lane = tid & 31, wid = tid >> 5;
    const int warp_m = (wid & 3) * 32, warp_n = (wid >> 2) * 32;
    const int bm = blockIdx.y * BMg, bn = blockIdx.x * BNg;
    const size_t Apl = (size_t)M * K;
    const size_t Bpl = (size_t)N * K;

    // loader decomposition: chunk row = tid>>2, k offset = (tid&3)*8 (16B chunk)
    const int lr = tid >> 2, lk = (tid & 3) << 3;
    const __nv_bfloat16* Ag = Ahl + (size_t)(bm + lr) * K + lk;
    const __nv_bfloat16* Bg = Bhl + (size_t)(bn + lr) * K + lk;

    const uint32_t smbase = (uint32_t)__cvta_generic_to_shared(sm);

    // ldmatrix lane decomposition
    const int q = lane & 7, tt = lane >> 3;
    const int a_row = warp_m + (tt & 1) * 8 + q;
    const int a_col = (tt >> 1) * 8;
    const int b_row = warp_n + (tt >> 1) * 8 + q;
    const int b_col = (tt & 1) * 8;

    float acc[2][4][4];
    #pragma unroll
    for (int i = 0; i < 2; i++)
        #pragma unroll
        for (int j = 0; j < 4; j++)
            #pragma unroll
            for (int r = 0; r < 4; r++) acc[i][j][r] = 0.f;

    auto issue = [&](int k0, int s) {
        uint32_t so = smbase + (uint32_t)s * (STAGE_E * 2);
        CP16(so + (lr * PITg + lk) * 2,                     Ag + k0);
        CP16(so + ((lr + 64) * PITg + lk) * 2,              Ag + (size_t)64 * K + k0);
        CP16(so + (A_OFF_L + lr * PITg + lk) * 2,           Ag + Apl + k0);
        CP16(so + (A_OFF_L + (lr + 64) * PITg + lk) * 2,    Ag + Apl + (size_t)64 * K + k0);
        CP16(so + (B_OFF_H + lr * PITg + lk) * 2,           Bg + k0);
        CP16(so + (B_OFF_L + lr * PITg + lk) * 2,           Bg + Bpl + k0);
    };

    auto compute = [&](int s) {
        const uint32_t off = (uint32_t)s * STAGE_E;
        #pragma unroll
        for (int kk = 0; kk < BKg; kk += 16) {
            uint32_t ah[2][4], al[2][4], bh[2][4], bl[2][4];
            #pragma unroll
            for (int mf = 0; mf < 2; mf++) {
                uint32_t ad = smbase + (off + (a_row + mf * 16) * PITg + kk + a_col) * 2;
                LDSM_X4(ah[mf][0], ah[mf][1], ah[mf][2], ah[mf][3], ad);
                LDSM_X4(al[mf][0], al[mf][1], al[mf][2], al[mf][3], ad + A_OFF_L * 2);
            }
            #pragma unroll
            for (int pf = 0; pf < 2; pf++) {
                uint32_t bd = smbase + (off + B_OFF_H + (b_row + pf * 16) * PITg + kk + b_col) * 2;
                LDSM_X4(bh[pf][0], bh[pf][1], bh[pf][2], bh[pf][3], bd);
                LDSM_X4(bl[pf][0], bl[pf][1], bl[pf][2], bl[pf][3], bd + (B_OFF_L - B_OFF_H) * 2);
            }
            // pass-major: 8 independent MMAs between accumulator reuses
            #pragma unroll
            for (int mf = 0; mf < 2; mf++)
                #pragma unroll
                for (int nf = 0; nf < 4; nf++)
                    MMA16816(acc[mf][nf], ah[mf], bh[nf >> 1][2 * (nf & 1)], bh[nf >> 1][2 * (nf & 1) + 1]);
            #pragma unroll
            for (int mf = 0; mf < 2; mf++)
                #pragma unroll
                for (int nf = 0; nf < 4; nf++)
                    MMA16816(acc[mf][nf], al[mf], bh[nf >> 1][2 * (nf & 1)], bh[nf >> 1][2 * (nf & 1) + 1]);
            #pragma unroll
            for (int mf = 0; mf < 2; mf++)
                #pragma unroll
                for (int nf = 0; nf < 4; nf++)
                    MMA16816(acc[mf][nf], ah[mf], bl[nf >> 1][2 * (nf & 1)], bl[nf >> 1][2 * (nf & 1) + 1]);
        }
    };

    const int nst = K / BKg;
    issue(0, 0); CPCOMMIT();
    issue(BKg, 1); CPCOMMIT();

    for (int s = 0; s < nst; s++) {
        if (s + 1 < nst) { CPWAIT1(); } else { CPWAIT0(); }
        __syncthreads();
        compute(s & 1);
        __syncthreads();
        if (s + 2 < nst) { issue((s + 2) * BKg, s & 1); CPCOMMIT(); }
    }

    const int g = lane >> 2, t2 = (lane & 3) * 2;
    #pragma unroll
    for (int mf = 0; mf < 2; mf++) {
        #pragma unroll
        for (int nf = 0; nf < 4; nf++) {
            int row = bm + warp_m + mf * 16 + g;
            int col = bn + warp_n + nf * 8 + t2;
            *(float2*)(Cm + (size_t)row * N + col)       = make_float2(acc[mf][nf][0], acc[mf][nf][1]);
            *(float2*)(Cm + (size_t)(row + 8) * N + col) = make_float2(acc[mf][nf][2], acc[mf][nf][3]);
        }
    }
}

// ---------------- per-channel BN stats ----------------
__global__ void bn_stats_kernel(const float* __restrict__ Hm, int N,
                                const float* __restrict__ gamma, const float* __restrict__ beta,
                                float* __restrict__ scale, float* __restrict__ shift)
{
    int o = blockIdx.x;
    const float* row = Hm + (size_t)o * N;
    float s = 0.f, sq = 0.f;
    for (int i = threadIdx.x; i < N; i += blockDim.x) {
        float v = row[i];
        s += v; sq = fmaf(v, v, sq);
    }
    __shared__ float sh1[256], sh2[256];
    sh1[threadIdx.x] = s; sh2[threadIdx.x] = sq;
    __syncthreads();
    for (int off = 128; off > 0; off >>= 1) {
        if (threadIdx.x < off) {
            sh1[threadIdx.x] += sh1[threadIdx.x + off];
            sh2[threadIdx.x] += sh2[threadIdx.x + off];
        }
        __syncthreads();
    }
    if (threadIdx.x == 0) {
        float invN = 1.0f / (float)N;
        float mu  = sh1[0] * invN;
        float var = sh2[0] * invN - mu * mu;
        float sc  = gamma[o] * rsqrtf(var + BN_EPS);
        scale[o] = sc;
        shift[o] = beta[o] - mu * sc;
    }
}

// ---------------- z_g extraction ----------------
__global__ void zg_kernel(const float* __restrict__ z, float* __restrict__ out)
{
    int i = blockIdx.x * blockDim.x + threadIdx.x;
    if (i >= BATCH * OUTC) return;
    int b = i / OUTC, ch = i % OUTC;
    out[OFF_ZG + i] = z[(size_t)ch * NN1 + b * L1];
}

// ---------------- 1/max(||z_feat||,eps) per (b,l) ----------------
__global__ void rnrm_kernel(const float* __restrict__ z, float* __restrict__ rnrm)
{
    int idx = blockIdx.x * blockDim.x + threadIdx.x;
    if (idx >= BATCH * LL) return;
    int b = idx / LL, l = idx % LL;
    const float* zp = z + (size_t)b * L1 + 1 + l;
    float s = 0.f;
    #pragma unroll 8
    for (int ch = 0; ch < OUTC; ch++) {
        float v = zp[(size_t)ch * NN1];
        s = fmaf(v, v, s);
    }
    rnrm[idx] = 1.0f / fmaxf(sqrtf(s), NORM_EPS);
}

// ---------------- softmax ----------------
__global__ void softmax_kernel(const float* __restrict__ z, const float* __restrict__ rnrm,
                               float* __restrict__ attn_s, float* __restrict__ out)
{
    int row = blockIdx.x;
    int b = row >> 8, ch = row & 255;
    int tid = threadIdx.x;
    const float* zp = z + (size_t)ch * NN1 + b * L1 + 1;
    const float* rp = rnrm + b * LL;

    float v0 = -1e30f, v1 = -1e30f;
    if (tid < LL)       v0 = zp[tid]       * rp[tid];
    if (tid + 128 < LL) v1 = zp[tid + 128] * rp[tid + 128];

    __shared__ float red[128];
    red[tid] = fmaxf(v0, v1);
    __syncthreads();
    for (int off = 64; off > 0; off >>= 1) {
        if (tid < off) red[tid] = fmaxf(red[tid], red[tid + off]);
        __syncthreads();
    }
    float m = red[0];
    __syncthreads();

    float e0 = (tid < LL)       ? expf(v0 - m) : 0.f;
    float e1 = (tid + 128 < LL) ? expf(v1 - m) : 0.f;
    red[tid] = e0 + e1;
    __syncthreads();
    for (int off = 64; off > 0; off >>= 1) {
        if (tid < off) red[tid] += red[tid + off];
        __syncthreads();
    }
    float inv = 1.0f / red[0];

    size_t base = (size_t)row * LL;
    if (tid < LL) {
        float a = e0 * inv;
        attn_s[base + tid] = a;
        out[OFF_ATTN  + base + tid] = a;
        out[OFF_ATTN2 + base + tid] = a;
    }
    if (tid + 128 < LL) {
        float a = e1 * inv;
        attn_s[base + tid + 128] = a;
        out[OFF_ATTN  + base + tid + 128] = a;
        out[OFF_ATTN2 + base + tid + 128] = a;
    }
}

// ---------------- obj_val einsum -> objT[n2][c] hi/lo (split + transposed) ----------------
__global__ __launch_bounds__(512)
void objval_kernel(const float* __restrict__ x, const float* __restrict__ attn,
                   __nv_bfloat16* __restrict__ objT)
{
    __shared__ float xs[16][LL];
    __shared__ float as[32][LL];
    int b  = blockIdx.z;
    int h  = blockIdx.y;
    int cg = blockIdx.x;
    int tid = threadIdx.x;

    const float* ap = attn + ((size_t)b * OUTC + h * CKEYS) * LL;
    for (int i = tid; i < 32 * LL; i += 512) as[i / LL][i % LL] = ap[i];
    const float* xp = x + ((size_t)b * CIN + h * 256 + cg * 16) * LL;
    for (int i = tid; i < 16 * LL; i += 512) xs[i / LL][i % LL] = xp[i];
    __syncthreads();

    int ci = tid & 15, k = tid >> 4;
    float acc = 0.f;
    #pragma unroll 4
    for (int l = 0; l < LL; l++) acc = fmaf(xs[ci][l], as[k][l], acc);

    int c = h * 256 + cg * 16 + ci;
    const size_t plane = (size_t)NN2 * CIN;
    size_t o = (size_t)(b * CKEYS + k) * CIN + c;
    __nv_bfloat16 hh, ll;
    split2(acc, hh, ll);
    objT[o] = hh; objT[plane + o] = ll;
}

// ---------------- final scatter of obj_val ----------------
__global__ void scatter_out_kernel(const float* __restrict__ ov, float* __restrict__ out)
{
    int i = blockIdx.x * blockDim.x + threadIdx.x;
    if (i >= BATCH * OUTC * CKEYS) return;
    int b = i / (OUTC * CKEYS);
    int r = i % (OUTC * CKEYS);
    int o2 = r / CKEYS, k = r % CKEYS;
    out[OFF_OBJVAL + i] = ov[(size_t)o2 * NN2 + b * CKEYS + k];
}

// ---------------- launch ----------------
extern "C" void kernel_launch(void* const* d_in, const int* in_sizes, int n_in,
                              void* d_out, int out_size)
{
    const float* x    = (const float*)d_in[0];
    const float* w1_p = (const float*)d_in[1];
    const float* g_p  = (const float*)d_in[2];
    const float* b_p  = (const float*)d_in[3];
    const float* w2_p = (const float*)d_in[4];
    const float* w1_o = (const float*)d_in[5];
    const float* g_o  = (const float*)d_in[6];
    const float* b_o  = (const float*)d_in[7];
    const float* w2_o = (const float*)d_in[8];
    float* out = (float*)d_out;

    __nv_bfloat16 *w1pT, *w2pT, *w1oT, *w2oT, *xcatT, *h1T, *objT, *h2T;
    float *h1, *z, *rn, *attn, *h2, *ov, *scale, *shift;
    cudaGetSymbolAddress((void**)&w1pT,  g_w1pT);
    cudaGetSymbolAddress((void**)&w2pT,  g_w2pT);
    cudaGetSymbolAddress((void**)&w1oT,  g_w1oT);
    cudaGetSymbolAddress((void**)&w2oT,  g_w2oT);
    cudaGetSymbolAddress((void**)&xcatT, g_xcatT);
    cudaGetSymbolAddress((void**)&h1T,   g_h1T);
    cudaGetSymbolAddress((void**)&objT,  g_objT);
    cudaGetSymbolAddress((void**)&h2T,   g_h2T);
    cudaGetSymbolAddress((void**)&h1,    g_h1);
    cudaGetSymbolAddress((void**)&z,     g_z);
    cudaGetSymbolAddress((void**)&rn,    g_rnrm);
    cudaGetSymbolAddress((void**)&attn,  g_attn);
    cudaGetSymbolAddress((void**)&h2,    g_h2);
    cudaGetSymbolAddress((void**)&ov,    g_ov);
    cudaGetSymbolAddress((void**)&scale, g_scale);
    cudaGetSymbolAddress((void**)&shift, g_shift);

    cudaFuncSetAttribute(gemm_ts_kernel,
                         cudaFuncAttributeMaxDynamicSharedMemorySize, SMEM_BYTES);

    // 0) weight splits
    split_kernel<<<(HID * CIN / 4 + 255) / 256, 256>>>(w1_p, w1pT, HID * CIN);
    split_kernel<<<(OUTC * HID / 4 + 255) / 256, 256>>>(w2_p, w2pT, OUTC * HID);
    split_kernel<<<(HID * CIN / 4 + 255) / 256, 256>>>(w1_o, w1oT, HID * CIN);
    split_kernel<<<(OUTC * HID / 4 + 255) / 256, 256>>>(w2_o, w2oT, OUTC * HID);

    // 1) xcatT = [mean | x] transposed + split
    xcat_prep_kernel<<<dim3(CIN / 32, BATCH), 256>>>(x, xcatT);

    // 2) h1 = w1_p @ xcat
    gemm_ts_kernel<<<dim3(NN1 / BNg, HID / BMg), 256, SMEM_BYTES>>>(
        w1pT, xcatT, h1, HID, NN1, CIN);

    // 3) BN stats
    bn_stats_kernel<<<HID, 256>>>(h1, NN1, g_p, b_p, scale, shift);

    // 3b) h1T = split(relu(bn(h1)))^T
    tbs_kernel<<<dim3(NN1 / 32, HID / 32), 256>>>(h1, HID, NN1, scale, shift, h1T);

    // 4) z = w2_p @ relu(bn(h1))
    gemm_ts_kernel<<<dim3(NN1 / BNg, OUTC / BMg), 256, SMEM_BYTES>>>(
        w2pT, h1T, z, OUTC, NN1, HID);

    // 5) z_g
    zg_kernel<<<(BATCH * OUTC + 255) / 256, 256>>>(z, out);

    // 6) 1/||z_feat||
    rnrm_kernel<<<(BATCH * LL + 255) / 256, 256>>>(z, rn);

    // 7) softmax
    softmax_kernel<<<BATCH * OUTC, 128>>>(z, rn, attn, out);

    // 8) obj_val einsum -> objT (split + transposed)
    objval_kernel<<<dim3(16, NHEADS, BATCH), 512>>>(x, attn, objT);

    // 9) h2 = w1_o @ objval
    gemm_ts_kernel<<<dim3(NN2 / BNg, HID / BMg), 256, SMEM_BYTES>>>(
        w1oT, objT, h2, HID, NN2, CIN);

    // 10) BN stats
    bn_stats_kernel<<<HID, 256>>>(h2, NN2, g_o, b_o, scale, shift);

    // 10b) h2T
    tbs_kernel<<<dim3(NN2 / 32, HID / 32), 256>>>(h2, HID, NN2, scale, shift, h2T);

    // 11) ov = w2_o @ relu(bn(h2))
    gemm_ts_kernel<<<dim3(NN2 / BNg, OUTC / BMg), 256, SMEM_BYTES>>>(
        w2oT, h2T, ov, OUTC, NN2, HID);

    // 12) scatter obj_val
    scatter_out_kernel<<<(BATCH * OUTC * CKEYS + 255) / 256, 256>>>(ov, out);
}

// round 13
// speedup vs baseline: 1.0024x; 1.0002x over previous
#include <cuda_runtime.h>
#include <cuda_bf16.h>
#include <cstdint>
#include <cstddef>

// ---------------- problem constants ----------------
#define BATCH   64
#define CIN     2048
#define LL      196
#define L1      197
#define HID     2048
#define OUTC    256
#define NHEADS  8
#define CKEYS   32
#define NN1     (BATCH * L1)    // 12608
#define NN2     (BATCH * CKEYS) // 2048
#define BN_EPS  1e-5f
#define NORM_EPS 1e-12f

// output layout: z_g | obj_val | obj_attn | obj_attn_raw
#define OFF_ZG      0
#define OFF_OBJVAL  (BATCH * OUTC)
#define OFF_ATTN    (OFF_OBJVAL + BATCH * OUTC * CKEYS)
#define OFF_ATTN2   (OFF_ATTN + BATCH * NHEADS * CKEYS * LL)

// ---------------- scratch (static; no allocs) ----------------
// bf16 hi/lo plane pairs (lo plane at +plane_size)
__device__ __align__(16) __nv_bfloat16 g_w1pT[2 * (size_t)HID * CIN];
__device__ __align__(16) __nv_bfloat16 g_w2pT[2 * (size_t)OUTC * HID];
__device__ __align__(16) __nv_bfloat16 g_w1oT[2 * (size_t)HID * CIN];
__device__ __align__(16) __nv_bfloat16 g_w2oT[2 * (size_t)OUTC * HID];
__device__ __align__(16) __nv_bfloat16 g_xcatT[2 * (size_t)NN1 * CIN];
__device__ __align__(16) __nv_bfloat16 g_h1T[2 * (size_t)NN1 * HID];
__device__ __align__(16) __nv_bfloat16 g_objT[2 * (size_t)NN2 * CIN];
__device__ __align__(16) __nv_bfloat16 g_h2T[2 * (size_t)NN2 * HID];
// fp32
__device__ __align__(16) float g_h1[(size_t)HID * NN1];
__device__ __align__(16) float g_z[(size_t)OUTC * NN1];
__device__ __align__(16) float g_rnrm[BATCH * LL];
__device__ __align__(16) float g_attn[(size_t)BATCH * OUTC * LL];
__device__ __align__(16) float g_h2[(size_t)HID * NN2];
__device__ __align__(16) float g_ov[(size_t)OUTC * NN2];
__device__ __align__(16) float g_scale[HID];
__device__ __align__(16) float g_shift[HID];

// ---------------- helpers ----------------
__device__ __forceinline__ void split2(float v, __nv_bfloat16& h, __nv_bfloat16& l) {
    h = __float2bfloat16(v);
    l = __float2bfloat16(v - __bfloat162float(h));
}

// ---------------- weight split (fp32 [M][K] -> bf16 hi/lo planes) ----------------
__global__ void split_kernel(const float* __restrict__ in, __nv_bfloat16* __restrict__ out, int n)
{
    int i = (blockIdx.x * blockDim.x + threadIdx.x) * 4;
    if (i >= n) return;
    float4 v = *(const float4*)(in + i);
    __nv_bfloat16 h0, l0, h1, l1, h2, l2, h3, l3;
    split2(v.x, h0, l0); split2(v.y, h1, l1);
    split2(v.z, h2, l2); split2(v.w, h3, l3);
    __nv_bfloat162* ph = (__nv_bfloat162*)(out + i);
    ph[0] = __nv_bfloat162(h0, h1); ph[1] = __nv_bfloat162(h2, h3);
    __nv_bfloat162* pl = (__nv_bfloat162*)(out + n + i);
    pl[0] = __nv_bfloat162(l0, l1); pl[1] = __nv_bfloat162(l2, l3);
}

// ---------------- xcat prep: x(b,c,l) -> xcatT[n=b*197+{0|1+l}][c] hi/lo ----------------
__global__ __launch_bounds__(256)
void xcat_prep_kernel(const float* __restrict__ x, __nv_bfloat16* __restrict__ xT)
{
    __shared__ float xs[32][197];
    int b = blockIdx.y, c0 = blockIdx.x * 32;
    const float* xp = x + ((size_t)b * CIN + c0) * LL;
    for (int i = threadIdx.x; i < 32 * LL; i += 256) {
        int ci = i / LL, l = i % LL;
        xs[ci][1 + l] = xp[(size_t)ci * LL + l];
    }
    __syncthreads();
    if (threadIdx.x < 32) {
        float s = 0.f;
        for (int l = 1; l <= LL; l++) s += xs[threadIdx.x][l];
        xs[threadIdx.x][0] = s * (1.0f / (float)LL);
    }
    __syncthreads();
    const size_t plane = (size_t)NN1 * CIN;
    for (int i = threadIdx.x; i < L1 * 32; i += 256) {
        int li = i >> 5, ci = i & 31;
        __nv_bfloat16 h, l;
        split2(xs[ci][li], h, l);
        size_t o = (size_t)(b * L1 + li) * CIN + c0 + ci;
        xT[o] = h; xT[plane + o] = l;
    }
}

// ---------------- transpose + BN + relu + split: H[o][n] -> Ht[n][o] hi/lo ----------------
__global__ __launch_bounds__(256)
void tbs_kernel(const float* __restrict__ H, int Mrows, int Ncols,
                const float* __restrict__ scale, const float* __restrict__ shift,
                __nv_bfloat16* __restrict__ Ht)
{
    __shared__ float t[32][33];
    int n0 = blockIdx.x * 32, o0 = blockIdx.y * 32;
    int tx = threadIdx.x & 31, ty = threadIdx.x >> 5;
    #pragma unroll
    for (int j = 0; j < 4; j++) {
        int o = o0 + ty + j * 8;
        float v = H[(size_t)o * Ncols + n0 + tx];
        t[ty + j * 8][tx] = fmaxf(fmaf(v, scale[o], shift[o]), 0.f);
    }
    __syncthreads();
    const size_t plane = (size_t)Ncols * Mrows;
    #pragma unroll
    for (int j = 0; j < 4; j++) {
        int n = n0 + ty + j * 8;
        __nv_bfloat16 h, l;
        split2(t[tx][ty + j * 8], h, l);
        size_t o = (size_t)n * Mrows + o0 + tx;
        Ht[o] = h; Ht[plane + o] = l;
    }
}

// ---------------- bf16-split tensor-core GEMM (cp.async, pass-major MMA) ----------------
// C(MxN) fp32 = A(MxK) * B(NxK)^T via hi/lo planes.
#define BMg 128
#define BNg 64
#define BKg 32
#define PITg 40
#define A_OFF_L 5120
#define B_OFF_H 10240
#define B_OFF_L 12800
#define STAGE_E 15360
#define SMEM_BYTES (2 * STAGE_E * 2)   // 61440

#define LDSM_X4(r0, r1, r2, r3, addr) \
    asm volatile("ldmatrix.sync.aligned.m8n8.x4.shared.b16 {%0,%1,%2,%3}, [%4];" \
        : "=r"(r0), "=r"(r1), "=r"(r2), "=r"(r3) : "r"(addr))

#define MMA16816(d, a, b0, b1) \
    asm volatile("mma.sync.aligned.m16n8k16.row.col.f32.bf16.bf16.f32 " \
        "{%0,%1,%2,%3},{%4,%5,%6,%7},{%8,%9},{%0,%1,%2,%3};" \
        : "+f"(d[0]), "+f"(d[1]), "+f"(d[2]), "+f"(d[3]) \
        : "r"(a[0]), "r"(a[1]), "r"(a[2]), "r"(a[3]), "r"(b0), "r"(b1))

#define CP16(dst, src) \
    asm volatile("cp.async.cg.shared.global [%0], [%1], 16;" :: "r"(dst), "l"(src))
#define CPCOMMIT() asm volatile("cp.async.commit_group;")
#define CPWAIT1()  asm volatile("cp.async.wait_group 1;")
#define CPWAIT0()  asm volatile("cp.async.wait_group 0;")

__global__ __launch_bounds__(256)
void gemm_ts_kernel(const __nv_bfloat16* __restrict__ Ahl,
                    const __nv_bfloat16* __restrict__ Bhl,
                    float* __restrict__ Cm, int M, int N, int K)
{
    extern __shared__ __align__(16) __nv_bfloat16 sm[];
    const int tid  = threadIdx.x;
    const int lane = tid & 31, wid = tid >> 5;
    const int warp_m = (wid & 3) * 32, warp_n = (wid >> 2) * 32;
    const int bm = blockIdx.y * BMg, bn = blockIdx.x * BNg;
    const size_t Apl = (size_t)M * K;
    const size_t Bpl = (size_t)N * K;

    // loader decomposition: chunk row = tid>>2, k offset = (tid&3)*8 (16B chunk)
    const int lr = tid >> 2, lk = (tid & 3) << 3;
    const __nv_bfloat16* Ag = Ahl + (size_t)(bm + lr) * K + lk;
    const __nv_bfloat16* Bg = Bhl + (size_t)(bn + lr) * K + lk;

    const uint32_t smbase = (uint32_t)__cvta_generic_to_shared(sm);

    // ldmatrix lane decomposition
    const int q = lane & 7, tt = lane >> 3;
    const int a_row = warp_m + (tt & 1) * 8 + q;
    const int a_col = (tt >> 1) * 8;
    const int b_row = warp_n + (tt >> 1) * 8 + q;
    const int b_col = (tt & 1) * 8;

    float acc[2][4][4];
    #pragma unroll
    for (int i = 0; i < 2; i++)
        #pragma unroll
        for (int j = 0; j < 4; j++)
            #pragma unroll
            for (int r = 0; r < 4; r++) acc[i][j][r] = 0.f;

    auto issue = [&](int k0, int s) {
        uint32_t so = smbase + (uint32_t)s * (STAGE_E * 2);
        CP16(so + (lr * PITg + lk) * 2,                     Ag + k0);
        CP16(so + ((lr + 64) * PITg + lk) * 2,              Ag + (size_t)64 * K + k0);
        CP16(so + (A_OFF_L + lr * PITg + lk) * 2,           Ag + Apl + k0);
        CP16(so + (A_OFF_L + (lr + 64) * PITg + lk) * 2,    Ag + Apl + (size_t)64 * K + k0);
        CP16(so + (B_OFF_H + lr * PITg + lk) * 2,           Bg + k0);
        CP16(so + (B_OFF_L + lr * PITg + lk) * 2,           Bg + Bpl + k0);
    };

    auto compute = [&](int s) {
        const uint32_t off = (uint32_t)s * STAGE_E;
        #pragma unroll
        for (int kk = 0; kk < BKg; kk += 16) {
            uint32_t ah[2][4], al[2][4], bh[2][4], bl[2][4];
            #pragma unroll
            for (int mf = 0; mf < 2; mf++) {
                uint32_t ad = smbase + (off + (a_row + mf * 16) * PITg + kk + a_col) * 2;
                LDSM_X4(ah[mf][0], ah[mf][1], ah[mf][2], ah[mf][3], ad);
                LDSM_X4(al[mf][0], al[mf][1], al[mf][2], al[mf][3], ad + A_OFF_L * 2);
            }
            #pragma unroll
            for (int pf = 0; pf < 2; pf++) {
                uint32_t bd = smbase + (off + B_OFF_H + (b_row + pf * 16) * PITg + kk + b_col) * 2;
                LDSM_X4(bh[pf][0], bh[pf][1], bh[pf][2], bh[pf][3], bd);
                LDSM_X4(bl[pf][0], bl[pf][1], bl[pf][2], bl[pf][3], bd + (B_OFF_L - B_OFF_H) * 2);
            }
            // pass-major: 8 independent MMAs between accumulator reuses
            #pragma unroll
            for (int mf = 0; mf < 2; mf++)
                #pragma unroll
                for (int nf = 0; nf < 4; nf++)
                    MMA16816(acc[mf][nf], ah[mf], bh[nf >> 1][2 * (nf & 1)], bh[nf >> 1][2 * (nf & 1) + 1]);
            #pragma unroll
            for (int mf = 0; mf < 2; mf++)
                #pragma unroll
                for (int nf = 0; nf < 4; nf++)
                    MMA16816(acc[mf][nf], al[mf], bh[nf >> 1][2 * (nf & 1)], bh[nf >> 1][2 * (nf & 1) + 1]);
            #pragma unroll
            for (int mf = 0; mf < 2; mf++)
                #pragma unroll
                for (int nf = 0; nf < 4; nf++)
                    MMA16816(acc[mf][nf], ah[mf], bl[nf >> 1][2 * (nf & 1)], bl[nf >> 1][2 * (nf & 1) + 1]);
        }
    };

    const int nst = K / BKg;
    issue(0, 0); CPCOMMIT();
    issue(BKg, 1); CPCOMMIT();

    for (int s = 0; s < nst; s++) {
        if (s + 1 < nst) { CPWAIT1(); } else { CPWAIT0(); }
        __syncthreads();
        compute(s & 1);
        __syncthreads();
        if (s + 2 < nst) { issue((s + 2) * BKg, s & 1); CPCOMMIT(); }
    }

    const int g = lane >> 2, t2 = (lane & 3) * 2;
    #pragma unroll
    for (int mf = 0; mf < 2; mf++) {
        #pragma unroll
        for (int nf = 0; nf < 4; nf++) {
            int row = bm + warp_m + mf * 16 + g;
            int col = bn + warp_n + nf * 8 + t2;
            *(float2*)(Cm + (size_t)row * N + col)       = make_float2(acc[mf][nf][0], acc[mf][nf][1]);
            *(float2*)(Cm + (size_t)(row + 8) * N + col) = make_float2(acc[mf][nf][2], acc[mf][nf][3]);
        }
    }
}

// ---------------- per-channel BN stats ----------------
__global__ void bn_stats_kernel(const float* __restrict__ Hm, int N,
                                const float* __restrict__ gamma, const float* __restrict__ beta,
                                float* __restrict__ scale, float* __restrict__ shift)
{
    int o = blockIdx.x;
    const float* row = Hm + (size_t)o * N;
    float s = 0.f, sq = 0.f;
    for (int i = threadIdx.x; i < N; i += blockDim.x) {
        float v = row[i];
        s += v; sq = fmaf(v, v, sq);
    }
    __shared__ float sh1[256], sh2[256];
    sh1[threadIdx.x] = s; sh2[threadIdx.x] = sq;
    __syncthreads();
    for (int off = 128; off > 0; off >>= 1) {
        if (threadIdx.x < off) {
            sh1[threadIdx.x] += sh1[threadIdx.x + off];
            sh2[threadIdx.x] += sh2[threadIdx.x + off];
        }
        __syncthreads();
    }
    if (threadIdx.x == 0) {
        float invN = 1.0f / (float)N;
        float mu  = sh1[0] * invN;
        float var = sh2[0] * invN - mu * mu;
        float sc  = gamma[o] * rsqrtf(var + BN_EPS);
        scale[o] = sc;
        shift[o] = beta[o] - mu * sc;
    }
}

// ---------------- z_g extraction ----------------
__global__ void zg_kernel(const float* __restrict__ z, float* __restrict__ out)
{
    int i = blockIdx.x * blockDim.x + threadIdx.x;
    if (i >= BATCH * OUTC) return;
    int b = i / OUTC, ch = i % OUTC;
    out[OFF_ZG + i] = z[(size_t)ch * NN1 + b * L1];
}

// ---------------- 1/max(||z_feat||,eps) per (b,l) ----------------
__global__ void rnrm_kernel(const float* __restrict__ z, float* __restrict__ rnrm)
{
    int idx = blockIdx.x * blockDim.x + threadIdx.x;
    if (idx >= BATCH * LL) return;
    int b = idx / LL, l = idx % LL;
    const float* zp = z + (size_t)b * L1 + 1 + l;
    float s = 0.f;
    #pragma unroll 8
    for (int ch = 0; ch < OUTC; ch++) {
        float v = zp[(size_t)ch * NN1];
        s = fmaf(v, v, s);
    }
    rnrm[idx] = 1.0f / fmaxf(sqrtf(s), NORM_EPS);
}

// ---------------- softmax ----------------
__global__ void softmax_kernel(const float* __restrict__ z, const float* __restrict__ rnrm,
                               float* __restrict__ attn_s, float* __restrict__ out)
{
    int row = blockIdx.x;
    int b = row >> 8, ch = row & 255;
    int tid = threadIdx.x;
    const float* zp = z + (size_t)ch * NN1 + b * L1 + 1;
    const float* rp = rnrm + b * LL;

    float v0 = -1e30f, v1 = -1e30f;
    if (tid < LL)       v0 = zp[tid]       * rp[tid];
    if (tid + 128 < LL) v1 = zp[tid + 128] * rp[tid + 128];

    __shared__ float red[128];
    red[tid] = fmaxf(v0, v1);
    __syncthreads();
    for (int off = 64; off > 0; off >>= 1) {
        if (tid < off) red[tid] = fmaxf(red[tid], red[tid + off]);
        __syncthreads();
    }
    float m = red[0];
    __syncthreads();

    float e0 = (tid < LL)       ? expf(v0 - m) : 0.f;
    float e1 = (tid + 128 < LL) ? expf(v1 - m) : 0.f;
    red[tid] = e0 + e1;
    __syncthreads();
    for (int off = 64; off > 0; off >>= 1) {
        if (tid < off) red[tid] += red[tid + off];
        __syncthreads();
    }
    float inv = 1.0f / red[0];

    size_t base = (size_t)row * LL;
    if (tid < LL) {
        float a = e0 * inv;
        attn_s[base + tid] = a;
        out[OFF_ATTN  + base + tid] = a;
        out[OFF_ATTN2 + base + tid] = a;
    }
    if (tid + 128 < LL) {
        float a = e1 * inv;
        attn_s[base + tid + 128] = a;
        out[OFF_ATTN  + base + tid + 128] = a;
        out[OFF_ATTN2 + base + tid + 128] = a;
    }
}

// ---------------- obj_val einsum -> objT[n2][c] hi/lo (split + transposed) ----------------
__global__ __launch_bounds__(512)
void objval_kernel(const float* __restrict__ x, const float* __restrict__ attn,
                   __nv_bfloat16* __restrict__ objT)
{
    __shared__ float xs[16][LL];
    __shared__ float as[32][LL];
    int b  = blockIdx.z;
    int h  = blockIdx.y;
    int cg = blockIdx.x;
    int tid = threadIdx.x;

    const float* ap = attn + ((size_t)b * OUTC + h * CKEYS) * LL;
    for (int i = tid; i < 32 * LL; i += 512) as[i / LL][i % LL] = ap[i];
    const float* xp = x + ((size_t)b * CIN + h * 256 + cg * 16) * LL;
    for (int i = tid; i < 16 * LL; i += 512) xs[i / LL][i % LL] = xp[i];
    __syncthreads();

    int ci = tid & 15, k = tid >> 4;
    float acc = 0.f;
    #pragma unroll 4
    for (int l = 0; l < LL; l++) acc = fmaf(xs[ci][l], as[k][l], acc);

    int c = h * 256 + cg * 16 + ci;
    const size_t plane = (size_t)NN2 * CIN;
    size_t o = (size_t)(b * CKEYS + k) * CIN + c;
    __nv_bfloat16 hh, ll;
    split2(acc, hh, ll);
    objT[o] = hh; objT[plane + o] = ll;
}

// ---------------- final scatter of obj_val ----------------
__global__ void scatter_out_kernel(const float* __restrict__ ov, float* __restrict__ out)
{
    int i = blockIdx.x * blockDim.x + threadIdx.x;
    if (i >= BATCH * OUTC * CKEYS) return;
    int b = i / (OUTC * CKEYS);
    int r = i % (OUTC * CKEYS);
    int o2 = r / CKEYS, k = r % CKEYS;
    out[OFF_OBJVAL + i] = ov[(size_t)o2 * NN2 + b * CKEYS + k];
}

// ---------------- launch ----------------
extern "C" void kernel_launch(void* const* d_in, const int* in_sizes, int n_in,
                              void* d_out, int out_size)
{
    const float* x    = (const float*)d_in[0];
    const float* w1_p = (const float*)d_in[1];
    const float* g_p  = (const float*)d_in[2];
    const float* b_p  = (const float*)d_in[3];
    const float* w2_p = (const float*)d_in[4];
    const float* w1_o = (const float*)d_in[5];
    const float* g_o  = (const float*)d_in[6];
    const float* b_o  = (const float*)d_in[7];
    const float* w2_o = (const float*)d_in[8];
    float* out = (float*)d_out;

    __nv_bfloat16 *w1pT, *w2pT, *w1oT, *w2oT, *xcatT, *h1T, *objT, *h2T;
    float *h1, *z, *rn, *attn, *h2, *ov, *scale, *shift;
    cudaGetSymbolAddress((void**)&w1pT,  g_w1pT);
    cudaGetSymbolAddress((void**)&w2pT,  g_w2pT);
    cudaGetSymbolAddress((void**)&w1oT,  g_w1oT);
    cudaGetSymbolAddress((void**)&w2oT,  g_w2oT);
    cudaGetSymbolAddress((void**)&xcatT, g_xcatT);
    cudaGetSymbolAddress((void**)&h1T,   g_h1T);
    cudaGetSymbolAddress((void**)&objT,  g_objT);
    cudaGetSymbolAddress((void**)&h2T,   g_h2T);
    cudaGetSymbolAddress((void**)&h1,    g_h1);
    cudaGetSymbolAddress((void**)&z,     g_z);
    cudaGetSymbolAddress((void**)&rn,    g_rnrm);
    cudaGetSymbolAddress((void**)&attn,  g_attn);
    cudaGetSymbolAddress((void**)&h2,    g_h2);
    cudaGetSymbolAddress((void**)&ov,    g_ov);
    cudaGetSymbolAddress((void**)&scale, g_scale);
    cudaGetSymbolAddress((void**)&shift, g_shift);

    cudaFuncSetAttribute(gemm_ts_kernel,
                         cudaFuncAttributeMaxDynamicSharedMemorySize, SMEM_BYTES);

    // 0) weight splits
    split_kernel<<<(HID * CIN / 4 + 255) / 256, 256>>>(w1_p, w1pT, HID * CIN);
    split_kernel<<<(OUTC * HID / 4 + 255) / 256, 256>>>(w2_p, w2pT, OUTC * HID);
    split_kernel<<<(HID * CIN / 4 + 255) / 256, 256>>>(w1_o, w1oT, HID * CIN);
    split_kernel<<<(OUTC * HID / 4 + 255) / 256, 256>>>(w2_o, w2oT, OUTC * HID);

    // 1) xcatT = [mean | x] transposed + split
    xcat_prep_kernel<<<dim3(CIN / 32, BATCH), 256>>>(x, xcatT);

    // 2) h1 = w1_p @ xcat
    gemm_ts_kernel<<<dim3(NN1 / BNg, HID / BMg), 256, SMEM_BYTES>>>(
        w1pT, xcatT, h1, HID, NN1, CIN);

    // 3) BN stats
    bn_stats_kernel<<<HID, 256>>>(h1, NN1, g_p, b_p, scale, shift);

    // 3b) h1T = split(relu(bn(h1)))^T
    tbs_kernel<<<dim3(NN1 / 32, HID / 32), 256>>>(h1, HID, NN1, scale, shift, h1T);

    // 4) z = w2_p @ relu(bn(h1))
    gemm_ts_kernel<<<dim3(NN1 / BNg, OUTC / BMg), 256, SMEM_BYTES>>>(
        w2pT, h1T, z, OUTC, NN1, HID);

    // 5) z_g
    zg_kernel<<<(BATCH * OUTC + 255) / 256, 256>>>(z, out);

    // 6) 1/||z_feat||
    rnrm_kernel<<<(BATCH * LL + 255) / 256, 256>>>(z, rn);

    // 7) softmax
    softmax_kernel<<<BATCH * OUTC, 128>>>(z, rn, attn, out);

    // 8) obj_val einsum -> objT (split + transposed)
    objval_kernel<<<dim3(16, NHEADS, BATCH), 512>>>(x, attn, objT);

    // 9) h2 = w1_o @ objval
    gemm_ts_kernel<<<dim3(NN2 / BNg, HID / BMg), 256, SMEM_BYTES>>>(
        w1oT, objT, h2, HID, NN2, CIN);

    // 10) BN stats
    bn_stats_kernel<<<HID, 256>>>(h2, NN2, g_o, b_o, scale, shift);

    // 10b) h2T
    tbs_kernel<<<dim3(NN2 / 32, HID / 32), 256>>>(h2, HID, NN2, scale, shift, h2T);

    // 11) ov = w2_o @ relu(bn(h2))
    gemm_ts_kernel<<<dim3(NN2 / BNg, OUTC / BMg), 256, SMEM_BYTES>>>(
        w2oT, h2T, ov, OUTC, NN2, HID);

    // 12) scatter obj_val
    scatter_out_kernel<<<(BATCH * OUTC * CKEYS + 255) / 256, 256>>>(ov, out);
}